// round 3
// baseline (speedup 1.0000x reference)
#include <cuda_runtime.h>
#include <math.h>

#define N 8192
#define D 512
#define NC 128
#define TS 128        // block tile (rows x cols)
#define KT 16         // K chunk in smem
#define NCH (D / KT)  // 32 chunks
#define NT 64         // number of 128-wide tiles (N / TS)

// ---------------- scratch (device globals: no allocations allowed) ----------
__device__ int   g_tgt[N];
__device__ int   g_hist[NC];
__device__ float g_diag[N];
__device__ float g_pos_part[(size_t)N * NT];   // 2 MB
__device__ float g_neg_part[(size_t)N * NT];   // 2 MB
__device__ float g_rowloss[N];
__device__ float g_last_ps[NT];                // last-row sum of positive sims
__device__ float g_last_pc[NT];                // last-row count of positives
__device__ float g_last_ns[NT];                // last-row sum of negative sims

// ---------------- targets dtype auto-detect + convert -----------------------
// jax reference declares int64 but (without x64) jax emits int32. If the
// buffer is int64 (LE), the int32 view is [t0,0,t1,0,...]: all odd words 0.
// For genuine int32 labels in [0,128) the false-positive prob is ~(1/128)^4096.
__global__ void k_cvt(const int* __restrict__ raw) {
    __shared__ int s_nonzero;
    if (threadIdx.x == 0) s_nonzero = 0;
    __syncthreads();
    for (int i = threadIdx.x; i < N / 2; i += blockDim.x)
        if (raw[2 * i + 1] != 0) atomicOr(&s_nonzero, 1);
    __syncthreads();
    bool is64 = (s_nonzero == 0);
    for (int i = threadIdx.x; i < N; i += blockDim.x)
        g_tgt[i] = is64 ? raw[2 * i] : raw[i];
}

// ---------------- class histogram -------------------------------------------
__global__ void k_hist() {
    __shared__ int h[NC];
    int t = threadIdx.x;
    if (t < NC) h[t] = 0;
    __syncthreads();
    for (int i = t; i < N; i += blockDim.x)
        atomicAdd(&h[g_tgt[i]], 1);
    __syncthreads();
    if (t < NC) g_hist[t] = h[t];
}

// ---------------- fp64 diagonal (sim_ii): knife-edge for sim < 1 test -------
__global__ void k_diag(const float* __restrict__ X) {
    int warp = threadIdx.x >> 5, lane = threadIdx.x & 31;
    int row = blockIdx.x * 8 + warp;
    if (row >= N) return;
    const float* xr = X + (size_t)row * D;
    double s = 0.0;
    #pragma unroll
    for (int k = lane; k < D; k += 32) {
        double v = (double)xr[k];
        s += v * v;
    }
    #pragma unroll
    for (int off = 16; off; off >>= 1)
        s += __shfl_xor_sync(0xffffffffu, s, off);
    if (lane == 0) g_diag[row] = (float)s;
}

// ---------------- fused GEMM + masked exp partial reduction -----------------
// Upper-triangle tiles only (rt <= ct). Each off-diagonal tile contributes to
// row partials of its rows AND (by symmetry) of its columns; exp computed once
// per pair. Double-buffered smem, 1 barrier per K-chunk, 2-deep reg prefetch.
__global__ __launch_bounds__(256, 2)
void k_main(const float* __restrict__ X) {
    const int ct = blockIdx.x, rt = blockIdx.y;
    if (rt > ct) return;                      // triangle only

    __shared__ float As[2][KT][TS];
    __shared__ float Bs[2][KT][TS];
    __shared__ float s_l[3];                  // transposed last-row stats

    const int row0 = rt * TS, col0 = ct * TS;
    const int tid = threadIdx.x;
    const int tc = tid & 15, tr = tid >> 4;

    if (tid < 3) s_l[tid] = 0.0f;             // visible after first barrier

    float acc[8][8];
    #pragma unroll
    for (int i = 0; i < 8; i++)
        #pragma unroll
        for (int j = 0; j < 8; j++) acc[i][j] = 0.0f;

    // loaders: 512 float4 per 128x16 tile per array; 256 threads -> 2 each
    const int rr  = tid >> 2;                 // 0..63
    const int kq4 = (tid & 3) * 4;            // 0,4,8,12
    const float* pA0 = X + (size_t)(row0 + rr) * D + kq4;
    const float* pA1 = pA0 + (size_t)64 * D;
    const float* pB0 = X + (size_t)(col0 + rr) * D + kq4;
    const float* pB1 = pB0 + (size_t)64 * D;

    float4 ra0, ra1, rb0, rb1;

    // chunk 0 -> buf 0
    ra0 = *(const float4*)(pA0); ra1 = *(const float4*)(pA1);
    rb0 = *(const float4*)(pB0); rb1 = *(const float4*)(pB1);
    {
        As[0][kq4 + 0][rr] = ra0.x; As[0][kq4 + 1][rr] = ra0.y;
        As[0][kq4 + 2][rr] = ra0.z; As[0][kq4 + 3][rr] = ra0.w;
        As[0][kq4 + 0][rr + 64] = ra1.x; As[0][kq4 + 1][rr + 64] = ra1.y;
        As[0][kq4 + 2][rr + 64] = ra1.z; As[0][kq4 + 3][rr + 64] = ra1.w;
        Bs[0][kq4 + 0][rr] = rb0.x; Bs[0][kq4 + 1][rr] = rb0.y;
        Bs[0][kq4 + 2][rr] = rb0.z; Bs[0][kq4 + 3][rr] = rb0.w;
        Bs[0][kq4 + 0][rr + 64] = rb1.x; Bs[0][kq4 + 1][rr + 64] = rb1.y;
        Bs[0][kq4 + 2][rr + 64] = rb1.z; Bs[0][kq4 + 3][rr + 64] = rb1.w;
    }
    // prefetch chunk 1 into regs
    ra0 = *(const float4*)(pA0 + KT); ra1 = *(const float4*)(pA1 + KT);
    rb0 = *(const float4*)(pB0 + KT); rb1 = *(const float4*)(pB1 + KT);
    __syncthreads();

    // mainloop: at iter i, regs hold chunk i+1; buf (i&1) holds chunk i
    #pragma unroll 1
    for (int i = 0; i < NCH; i++) {
        const int cur = i & 1;
        if (i + 1 < NCH) {
            const int nxt = cur ^ 1;
            As[nxt][kq4 + 0][rr] = ra0.x; As[nxt][kq4 + 1][rr] = ra0.y;
            As[nxt][kq4 + 2][rr] = ra0.z; As[nxt][kq4 + 3][rr] = ra0.w;
            As[nxt][kq4 + 0][rr + 64] = ra1.x; As[nxt][kq4 + 1][rr + 64] = ra1.y;
            As[nxt][kq4 + 2][rr + 64] = ra1.z; As[nxt][kq4 + 3][rr + 64] = ra1.w;
            Bs[nxt][kq4 + 0][rr] = rb0.x; Bs[nxt][kq4 + 1][rr] = rb0.y;
            Bs[nxt][kq4 + 2][rr] = rb0.z; Bs[nxt][kq4 + 3][rr] = rb0.w;
            Bs[nxt][kq4 + 0][rr + 64] = rb1.x; Bs[nxt][kq4 + 1][rr + 64] = rb1.y;
            Bs[nxt][kq4 + 2][rr + 64] = rb1.z; Bs[nxt][kq4 + 3][rr + 64] = rb1.w;
            if (i + 2 < NCH) {
                const int off = (i + 2) * KT;
                ra0 = *(const float4*)(pA0 + off); ra1 = *(const float4*)(pA1 + off);
                rb0 = *(const float4*)(pB0 + off); rb1 = *(const float4*)(pB1 + off);
            }
        }
        #pragma unroll
        for (int kk = 0; kk < KT; kk++) {
            float aR[8], bR[8];
            *(float4*)(aR)     = *(const float4*)&As[cur][kk][tr * 8];
            *(float4*)(aR + 4) = *(const float4*)&As[cur][kk][tr * 8 + 4];
            *(float4*)(bR)     = *(const float4*)&Bs[cur][kk][tc * 8];
            *(float4*)(bR + 4) = *(const float4*)&Bs[cur][kk][tc * 8 + 4];
            #pragma unroll
            for (int ii = 0; ii < 8; ii++)
                #pragma unroll
                for (int jj = 0; jj < 8; jj++)
                    acc[ii][jj] = fmaf(aR[ii], bR[jj], acc[ii][jj]);
        }
        __syncthreads();
    }

    // ---------- epilogue ----------
    const int rbase = row0 + tr * 8;
    const int cbase = col0 + tc * 8;
    const bool isDiag = (rt == ct);
    int ti[8], tj[8];
    #pragma unroll
    for (int i = 0; i < 8; i++) ti[i] = g_tgt[rbase + i];
    #pragma unroll
    for (int j = 0; j < 8; j++) tj[j] = g_tgt[cbase + j];

    float psum[8], nsum[8], cp[8], cn[8];
    #pragma unroll
    for (int i = 0; i < 8; i++) { psum[i] = nsum[i] = cp[i] = cn[i] = 0.0f; }
    float lps = 0.0f, lpc = 0.0f, lns = 0.0f;     // diag-block last row (direct)
    float lpsT = 0.0f, lpcT = 0.0f, lnsT = 0.0f;  // transposed last-"row" stats

    const bool tcolLast = (ct == NT - 1) && !isDiag && (tc == 15); // col 8191 owner

    #pragma unroll
    for (int i = 0; i < 8; i++) {
        const int gr = rbase + i;
        const bool isLast = isDiag && (gr == N - 1);
        #pragma unroll
        for (int j = 0; j < 8; j++) {
            float s = acc[i][j];
            if (isDiag && gr == cbase + j) s = g_diag[gr]; // accurate diagonal
            if (ti[i] == tj[j]) {
                if (s < 1.0f) {
                    float e = __expf(1.0f - s);
                    psum[i] += e; cp[j] += e;
                    if (isLast) { lps += s; lpc += 1.0f; }
                    if (tcolLast && j == 7) { lpsT += s; lpcT += 1.0f; }
                }
            } else {
                float e = __expf(s);
                nsum[i] += e; cn[j] += e;
                if (isLast) lns += s;
                if (tcolLast && j == 7) lnsT += s;
            }
        }
    }

    // row-direction reduce over the 16 column-fragment lanes
    #pragma unroll
    for (int i = 0; i < 8; i++) {
        float p = psum[i], q = nsum[i];
        #pragma unroll
        for (int off = 8; off; off >>= 1) {
            p += __shfl_xor_sync(0xffffffffu, p, off, 16);
            q += __shfl_xor_sync(0xffffffffu, q, off, 16);
        }
        if (tc == 0) {
            g_pos_part[(size_t)(rbase + i) * NT + ct] = p;
            g_neg_part[(size_t)(rbase + i) * NT + ct] = q;
        }
    }

    // diag-block last-row (row 8191 lives in warp 7 of block (63,63))
    if (isDiag && rt == NT - 1 && (tid >> 5) == 7) {
        #pragma unroll
        for (int off = 16; off; off >>= 1) {
            lps += __shfl_xor_sync(0xffffffffu, lps, off);
            lpc += __shfl_xor_sync(0xffffffffu, lpc, off);
            lns += __shfl_xor_sync(0xffffffffu, lns, off);
        }
        if ((tid & 31) == 0) {
            g_last_ps[NT - 1] = lps;
            g_last_pc[NT - 1] = lpc;
            g_last_ns[NT - 1] = lns;
        }
    }

    if (isDiag) return;   // diagonal tiles: direct direction covers everything

    // transposed last-row stats -> shared accumulators
    if (tcolLast) {
        atomicAdd(&s_l[0], lpsT);
        atomicAdd(&s_l[1], lpcT);
        atomicAdd(&s_l[2], lnsT);
    }

    // column-direction reduce: stage per-thread column partials in smem
    // (safe: final mainloop iteration ended with __syncthreads())
    float* Pbuf = &As[0][0][0];   // [16][128] view
    float* Nbuf = &Bs[0][0][0];
    #pragma unroll
    for (int j = 0; j < 8; j++) {
        Pbuf[tr * TS + tc * 8 + j] = cp[j];
        Nbuf[tr * TS + tc * 8 + j] = cn[j];
    }
    __syncthreads();

    if (tid < TS) {
        float p = 0.0f, q = 0.0f;
        #pragma unroll
        for (int t2 = 0; t2 < 16; t2++) {
            p += Pbuf[t2 * TS + tid];
            q += Nbuf[t2 * TS + tid];
        }
        g_pos_part[(size_t)(col0 + tid) * NT + rt] = p;
        g_neg_part[(size_t)(col0 + tid) * NT + rt] = q;
    }
    if (tid == 0 && ct == NT - 1) {
        g_last_ps[rt] = s_l[0];
        g_last_pc[rt] = s_l[1];
        g_last_ns[rt] = s_l[2];
    }
}

// ---------------- per-row: sum partials, take logs ---------------------------
__global__ void k_reduce() {
    int r = blockIdx.x * blockDim.x + threadIdx.x;   // 64 x 128 = 8192
    if (r >= N) return;
    const float4* pp = (const float4*)(g_pos_part + (size_t)r * NT);
    const float4* nn = (const float4*)(g_neg_part + (size_t)r * NT);
    float p = 0.0f, q = 0.0f;
    #pragma unroll
    for (int i = 0; i < NT / 4; i++) {
        float4 a = pp[i]; p += (a.x + a.y) + (a.z + a.w);
        float4 b = nn[i]; q += (b.x + b.y) + (b.z + b.w);
    }
    bool hasneg = g_hist[g_tgt[r]] < N;
    g_rowloss[r] = hasneg ? (logf(p) + logf(q)) : 0.0f;
}

// ---------------- final scalars ----------------------------------------------
__global__ void k_final(float* __restrict__ out) {
    __shared__ float sl[256];
    __shared__ int   sc[256];
    int t = threadIdx.x;
    float s = 0.0f; int c = 0;
    for (int r = t; r < N; r += 256) {
        s += g_rowloss[r];
        if (g_hist[g_tgt[r]] >= N) c++;      // row skipped (no negatives)
    }
    sl[t] = s; sc[t] = c;
    __syncthreads();
    for (int off = 128; off; off >>= 1) {
        if (t < off) { sl[t] += sl[t + off]; sc[t] += sc[t + off]; }
        __syncthreads();
    }
    if (t == 0) {
        float lps = 0.0f, lpc = 0.0f, lns = 0.0f;
        for (int i = 0; i < NT; i++) {
            lps += g_last_ps[i]; lpc += g_last_pc[i]; lns += g_last_ns[i];
        }
        int negcnt = N - g_hist[g_tgt[N - 1]];
        out[0] = sl[0] / (float)N;                 // loss
        out[1] = (float)sc[0] / (float)N;          // prec
        out[2] = lps / lpc;                        // mean_pos_sim (last row)
        out[3] = lns / (float)negcnt;              // mean_neg_sim (last row)
    }
}

// ---------------- launch ------------------------------------------------------
extern "C" void kernel_launch(void* const* d_in, const int* in_sizes, int n_in,
                              void* d_out, int out_size) {
    const float* X   = (const float*)d_in[0];
    const int*   raw = (const int*)d_in[1];     // int32 or int64, auto-detected
    float*       out = (float*)d_out;
    (void)in_sizes; (void)n_in; (void)out_size;

    k_cvt<<<1, 256>>>(raw);
    k_hist<<<1, 256>>>();
    k_diag<<<N / 8, 256>>>(X);
    dim3 grid(NT, NT);
    k_main<<<grid, 256>>>(X);
    k_reduce<<<NT, 128>>>();
    k_final<<<1, 256>>>(out);
}

// round 8
// speedup vs baseline: 1.3447x; 1.3447x over previous
#include <cuda_runtime.h>
#include <cuda_bf16.h>
#include <math.h>
#include <stdint.h>

#define N 8192
#define D 512
#define NC 128
#define NPART 128         // partials per row: 64 col-tiles x 2 warp col-halves

#define TM 128            // CTA tile rows
#define TN 128            // CTA tile cols
#define KC 64             // K chunk (bf16) = 128 B/row
#define NCH (D / KC)      // 8 chunks
#define GX (N / TN)       // 64
#define GY (N / TM)       // 64

// ---------------- scratch (device globals; no allocations allowed) ----------
__device__ int   g_tgt[N];
__device__ int   g_hist[NC];
__device__ float g_diag[N];
__device__ uint4 g_Xhi[(size_t)N * D / 8];   // bf16 hi parts, row-major
__device__ uint4 g_Xlo[(size_t)N * D / 8];   // bf16 lo parts
__device__ float g_pos_part[(size_t)N * NPART];   // 4 MB
__device__ float g_neg_part[(size_t)N * NPART];   // 4 MB
__device__ float g_rowloss[N];
__device__ float g_last_ps[NPART];
__device__ float g_last_pc[NPART];
__device__ float g_last_ns[NPART];

// ---------------- PTX helpers (ALL baseline PTX: sm_80+/sm_75+) -------------
__device__ __forceinline__ uint32_t smem_to_u32(const void* p) {
    uint32_t a;
    asm("{ .reg .u64 t; cvta.to.shared.u64 t, %1; cvt.u32.u64 %0, t; }"
        : "=r"(a) : "l"(p));
    return a;
}
#define CP16(sm, gp) \
    asm volatile("cp.async.cg.shared.global [%0], [%1], 16;" \
                 :: "r"(sm), "l"(gp) : "memory")
#define CP_COMMIT() asm volatile("cp.async.commit_group;" ::: "memory")
#define CP_WAIT0()  asm volatile("cp.async.wait_group 0;" ::: "memory")
#define LDSM_X4(r0, r1, r2, r3, a) \
    asm volatile("ldmatrix.sync.aligned.m8n8.x4.shared.b16 {%0,%1,%2,%3}, [%4];" \
                 : "=r"(r0), "=r"(r1), "=r"(r2), "=r"(r3) : "r"(a))
__device__ __forceinline__ void mma_bf16(float& c0, float& c1, float& c2, float& c3,
                                         uint32_t a0, uint32_t a1, uint32_t a2, uint32_t a3,
                                         uint32_t b0, uint32_t b1) {
    asm volatile("mma.sync.aligned.m16n8k16.row.col.f32.bf16.bf16.f32 "
                 "{%0,%1,%2,%3},{%4,%5,%6,%7},{%8,%9},{%0,%1,%2,%3};"
                 : "+f"(c0), "+f"(c1), "+f"(c2), "+f"(c3)
                 : "r"(a0), "r"(a1), "r"(a2), "r"(a3), "r"(b0), "r"(b1));
}
#define SWZ(o) ((o) ^ (((o) >> 3) & 0x70))

// smem layout (dynamic): 2 stages x {Ahi,Alo,Bhi,Blo} x 16 KB + col targets
#define TILE_B   16384
#define SM_A(st, hl) (((st) * 2 + (hl)) * TILE_B)
#define SM_B(st, hl) (65536 + ((st) * 2 + (hl)) * TILE_B)
#define SM_TGT   131072
#define SMEM_TOTAL (131072 + 512)

// ---------------- targets dtype auto-detect + convert -----------------------
// jax reference declares int64 but (without x64) jax emits int32. If the
// buffer is int64 (LE), the int32 view is [t0,0,t1,0,...]: all odd words 0.
__global__ void k_cvt(const int* __restrict__ raw) {
    __shared__ int s_nonzero;
    if (threadIdx.x == 0) s_nonzero = 0;
    __syncthreads();
    for (int i = threadIdx.x; i < N / 2; i += blockDim.x)
        if (raw[2 * i + 1] != 0) atomicOr(&s_nonzero, 1);
    __syncthreads();
    bool is64 = (s_nonzero == 0);
    for (int i = threadIdx.x; i < N; i += blockDim.x)
        g_tgt[i] = is64 ? raw[2 * i] : raw[i];
}

// ---------------- class histogram -------------------------------------------
__global__ void k_hist() {
    __shared__ int h[NC];
    int t = threadIdx.x;
    if (t < NC) h[t] = 0;
    __syncthreads();
    for (int i = t; i < N; i += blockDim.x) atomicAdd(&h[g_tgt[i]], 1);
    __syncthreads();
    if (t < NC) g_hist[t] = h[t];
}

// ---------------- fp64 diagonal (knife-edge for sim < 1) --------------------
__global__ void k_diag(const float* __restrict__ X) {
    int warp = threadIdx.x >> 5, lane = threadIdx.x & 31;
    int row = blockIdx.x * 8 + warp;
    if (row >= N) return;
    const float* xr = X + (size_t)row * D;
    double s = 0.0;
    for (int k = lane; k < D; k += 32) { double v = (double)xr[k]; s += v * v; }
    #pragma unroll
    for (int off = 16; off; off >>= 1) s += __shfl_xor_sync(0xffffffffu, s, off);
    if (lane == 0) g_diag[row] = (float)s;
}

// ---------------- fp32 -> bf16 hi/lo split ----------------------------------
__global__ void k_split(const float* __restrict__ X) {
    size_t i = (size_t)blockIdx.x * blockDim.x + threadIdx.x;   // 524288 threads
    const float4* x4 = (const float4*)X;
    float4 v0 = x4[2 * i], v1 = x4[2 * i + 1];
    float f[8] = {v0.x, v0.y, v0.z, v0.w, v1.x, v1.y, v1.z, v1.w};
    unsigned int h[4], l[4];
    #pragma unroll
    for (int j = 0; j < 4; j++) {
        __nv_bfloat16 h0 = __float2bfloat16(f[2*j]);
        __nv_bfloat16 h1 = __float2bfloat16(f[2*j + 1]);
        __nv_bfloat16 l0 = __float2bfloat16(f[2*j]     - __bfloat162float(h0));
        __nv_bfloat16 l1 = __float2bfloat16(f[2*j + 1] - __bfloat162float(h1));
        h[j] = (uint32_t)__bfloat16_as_ushort(h0) | ((uint32_t)__bfloat16_as_ushort(h1) << 16);
        l[j] = (uint32_t)__bfloat16_as_ushort(l0) | ((uint32_t)__bfloat16_as_ushort(l1) << 16);
    }
    g_Xhi[i] = make_uint4(h[0], h[1], h[2], h[3]);
    g_Xlo[i] = make_uint4(l[0], l[1], l[2], l[3]);
}

// ---------------- HMMA fused GEMM + masked exp epilogue ---------------------
// D[128x128] = Ah·Bh^T + Ah·Bl^T + Al·Bh^T (fp32 acc), 8 warps in 4x2,
// warp tile 32x64, cp.async double-buffered smem, ldmatrix fragments.
__global__ __launch_bounds__(256, 1) void k_hmma() {
    extern __shared__ char smem[];
    const uint32_t sb = smem_to_u32(smem);
    const int tid = threadIdx.x;
    const int wid = tid >> 5, lane = tid & 31;
    const int ct = blockIdx.x, rt = blockIdx.y;
    const int row0 = rt * TM, col0 = ct * TN;
    const int wr0 = (wid >> 1) * 32;          // warp row offset in tile
    const int cb  = wid & 1;                  // warp col-half
    const int wc0 = cb * 64;

    int* s_tgt = (int*)(smem + SM_TGT);
    if (tid < TN) s_tgt[tid] = g_tgt[col0 + tid];

    float acc[2][8][4];
    #pragma unroll
    for (int t = 0; t < 2; t++)
        #pragma unroll
        for (int u = 0; u < 8; u++)
            #pragma unroll
            for (int e = 0; e < 4; e++) acc[t][u][e] = 0.0f;

    const char* pXh = (const char*)g_Xhi;
    const char* pXl = (const char*)g_Xlo;
    const int r_ld = tid >> 3;                // 0..31 base row for loads
    const int g_ld = (tid & 7) * 16;          // granule byte offset

    // issue cp.async for chunk c into stage st (16 x 16B per thread)
    #define ISSUE(c, st) do {                                                  \
        const size_t kb_ = (size_t)(c) * 128;                                  \
        _Pragma("unroll")                                                      \
        for (int j_ = 0; j_ < 4; j_++) {                                       \
            int r_ = r_ld + j_ * 32;                                           \
            uint32_t sw_ = SWZ((uint32_t)(r_ * 128 + g_ld));                   \
            size_t ga_ = (size_t)(row0 + r_) * 1024 + kb_ + g_ld;              \
            size_t gb_ = (size_t)(col0 + r_) * 1024 + kb_ + g_ld;              \
            CP16(sb + SM_A(st, 0) + sw_, pXh + ga_);                           \
            CP16(sb + SM_A(st, 1) + sw_, pXl + ga_);                           \
            CP16(sb + SM_B(st, 0) + sw_, pXh + gb_);                           \
            CP16(sb + SM_B(st, 1) + sw_, pXl + gb_);                           \
        }                                                                      \
        CP_COMMIT();                                                           \
    } while (0)

    ISSUE(0, 0);
    for (int c = 0; c < NCH; c++) {
        const int st = c & 1;
        CP_WAIT0();
        __syncthreads();                      // stage st data visible; prior
                                              // stage's MMA done by all warps
        if (c + 1 < NCH) ISSUE(c + 1, st ^ 1);

        #pragma unroll
        for (int s = 0; s < 4; s++) {         // 4 k16-steps per chunk
            const int kb = s * 32;
            uint32_t ah[2][4], al[2][4];
            #pragma unroll
            for (int t = 0; t < 2; t++) {
                int r = wr0 + t * 16 + (lane & 15);
                uint32_t off = (uint32_t)(r * 128 + kb + 16 * (lane >> 4));
                uint32_t sw = SWZ(off);
                LDSM_X4(ah[t][0], ah[t][1], ah[t][2], ah[t][3], sb + SM_A(st, 0) + sw);
                LDSM_X4(al[t][0], al[t][1], al[t][2], al[t][3], sb + SM_A(st, 1) + sw);
            }
            uint32_t bh[8][2], bl[8][2];
            #pragma unroll
            for (int p = 0; p < 4; p++) {     // each x4 covers 2 n8-tiles
                int n = wc0 + p * 16 + (lane & 7) + 8 * (lane >> 4);
                uint32_t off = (uint32_t)(n * 128 + kb + 16 * ((lane >> 3) & 1));
                uint32_t sw = SWZ(off);
                LDSM_X4(bh[2*p][0], bh[2*p][1], bh[2*p+1][0], bh[2*p+1][1],
                        sb + SM_B(st, 0) + sw);
                LDSM_X4(bl[2*p][0], bl[2*p][1], bl[2*p+1][0], bl[2*p+1][1],
                        sb + SM_B(st, 1) + sw);
            }
            #pragma unroll
            for (int t = 0; t < 2; t++)
                #pragma unroll
                for (int u = 0; u < 8; u++) {
                    mma_bf16(acc[t][u][0], acc[t][u][1], acc[t][u][2], acc[t][u][3],
                             ah[t][0], ah[t][1], ah[t][2], ah[t][3], bh[u][0], bh[u][1]);
                    mma_bf16(acc[t][u][0], acc[t][u][1], acc[t][u][2], acc[t][u][3],
                             ah[t][0], ah[t][1], ah[t][2], ah[t][3], bl[u][0], bl[u][1]);
                    mma_bf16(acc[t][u][0], acc[t][u][1], acc[t][u][2], acc[t][u][3],
                             al[t][0], al[t][1], al[t][2], al[t][3], bh[u][0], bh[u][1]);
                }
        }
    }

    // ---------- epilogue: masks + exp + quad-reduced row partials ----------
    // C frag: lane holds rows (wr0+t*16+rg*8+lane/4), cols 2*(lane&3)+e of tile u
    #pragma unroll
    for (int t = 0; t < 2; t++) {
        #pragma unroll
        for (int rg = 0; rg < 2; rg++) {
            const int gr = row0 + wr0 + t * 16 + rg * 8 + (lane >> 2);
            const int tr = g_tgt[gr];
            const float dg = g_diag[gr];
            float ps = 0.0f, ns = 0.0f, lp = 0.0f, lc = 0.0f, ln = 0.0f;
            #pragma unroll
            for (int u = 0; u < 8; u++) {
                #pragma unroll
                for (int e = 0; e < 2; e++) {
                    const int lc_col = wc0 + u * 8 + 2 * (lane & 3) + e;
                    float s = acc[t][u][rg * 2 + e];
                    if (col0 + lc_col == gr) s = dg;        // accurate diagonal
                    const int tj = s_tgt[lc_col];
                    if (tj == tr) {
                        if (s < 1.0f) { ps += __expf(1.0f - s); lp += s; lc += 1.0f; }
                    } else {
                        ns += __expf(s); ln += s;
                    }
                }
            }
            // reduce over the 4 lanes sharing this row (lane&3 = 0..3)
            #pragma unroll
            for (int off = 1; off <= 2; off <<= 1) {
                ps += __shfl_xor_sync(0xffffffffu, ps, off);
                ns += __shfl_xor_sync(0xffffffffu, ns, off);
                lp += __shfl_xor_sync(0xffffffffu, lp, off);
                lc += __shfl_xor_sync(0xffffffffu, lc, off);
                ln += __shfl_xor_sync(0xffffffffu, ln, off);
            }
            if ((lane & 3) == 0) {
                const size_t slot = (size_t)gr * NPART + ct * 2 + cb;
                g_pos_part[slot] = ps;
                g_neg_part[slot] = ns;
                if (gr == N - 1) {            // unique writer per (ct, cb)
                    g_last_ps[ct * 2 + cb] = lp;
                    g_last_pc[ct * 2 + cb] = lc;
                    g_last_ns[ct * 2 + cb] = ln;
                }
            }
        }
    }
}

// ---------------- per-row: sum partials, take logs ---------------------------
__global__ void k_reduce() {
    int r = blockIdx.x * blockDim.x + threadIdx.x;
    if (r >= N) return;
    const float4* pp = (const float4*)(g_pos_part + (size_t)r * NPART);
    const float4* nn = (const float4*)(g_neg_part + (size_t)r * NPART);
    float p = 0.0f, q = 0.0f;
    #pragma unroll
    for (int i = 0; i < NPART / 4; i++) {
        float4 a = pp[i]; p += (a.x + a.y) + (a.z + a.w);
        float4 b = nn[i]; q += (b.x + b.y) + (b.z + b.w);
    }
    bool hasneg = g_hist[g_tgt[r]] < N;
    g_rowloss[r] = hasneg ? (logf(p) + logf(q)) : 0.0f;
}

// ---------------- final scalars ----------------------------------------------
__global__ void k_final(float* __restrict__ out) {
    __shared__ float sl[256];
    __shared__ int   sc[256];
    int t = threadIdx.x;
    float s = 0.0f; int c = 0;
    for (int r = t; r < N; r += 256) {
        s += g_rowloss[r];
        if (g_hist[g_tgt[r]] >= N) c++;
    }
    sl[t] = s; sc[t] = c;
    __syncthreads();
    for (int off = 128; off; off >>= 1) {
        if (t < off) { sl[t] += sl[t + off]; sc[t] += sc[t + off]; }
        __syncthreads();
    }
    if (t == 0) {
        float lps = 0.0f, lpc = 0.0f, lns = 0.0f;
        for (int i = 0; i < NPART; i++) {
            lps += g_last_ps[i]; lpc += g_last_pc[i]; lns += g_last_ns[i];
        }
        int negcnt = N - g_hist[g_tgt[N - 1]];
        out[0] = sl[0] / (float)N;                 // loss
        out[1] = (float)sc[0] / (float)N;          // prec
        out[2] = lps / lpc;                        // mean_pos_sim (last row)
        out[3] = lns / (float)negcnt;              // mean_neg_sim (last row)
    }
}

// ---------------- launch ------------------------------------------------------
extern "C" void kernel_launch(void* const* d_in, const int* in_sizes, int n_in,
                              void* d_out, int out_size) {
    const float* X   = (const float*)d_in[0];
    const int*   raw = (const int*)d_in[1];     // int32 or int64, auto-detected
    float*       out = (float*)d_out;
    (void)in_sizes; (void)n_in; (void)out_size;

    cudaFuncSetAttribute(k_hmma, cudaFuncAttributeMaxDynamicSharedMemorySize, SMEM_TOTAL);

    k_cvt<<<1, 256>>>(raw);
    k_hist<<<1, 256>>>();
    k_diag<<<N / 8, 256>>>(X);
    k_split<<<(N * D / 8) / 256, 256>>>(X);
    dim3 grid(GX, GY);
    k_hmma<<<grid, 256, SMEM_TOTAL>>>();
    k_reduce<<<N / 128, 128>>>();
    k_final<<<1, 256>>>(out);
}